// round 1
// baseline (speedup 1.0000x reference)
#include <cuda_runtime.h>

// ---------------------------------------------------------------------------
// PENN layer: message-passing GNN block.
//   X1 = [h[src] || h[dst] || e] @ W1 + b1            [E,128]  (+ col stats)
//   msg = relu(BN(X1)) @ W2 + b2 ; agg = scatter_sum(msg, dst)  [N,128]
//   Y  = [h || agg] @ W3 + b3                          [N,128]  (+ col stats)
//   hn = relu(BN(Y)) @ W4 + b4 ; out = LayerNorm(h + hn)        [N,128]
// ---------------------------------------------------------------------------

static constexpr int MAXE = 640000;
static constexpr int MAXN = 50000;

// Scratch (allocation-free rule: __device__ globals)
__device__ __align__(16) float g_X1[(size_t)MAXE * 128];   // 327.68 MB
__device__ __align__(16) float g_Y [(size_t)MAXN * 128];   // 25.6 MB
__device__ __align__(16) float g_agg[(size_t)MAXN * 128];  // 25.6 MB
__device__ double g_s1[128], g_q1[128], g_s2[128], g_q2[128];
__device__ float  g_scale1[128], g_shift1[128], g_scale2[128], g_shift2[128];

struct GP {
    const float* h;
    const float* ea;
    const float* W;
    const float* bias;
    const int*   src;
    const int*   dst;
    const float* lng;
    const float* lnb;
    float*       out;
    int          M;
};

__global__ void zero_kernel(int Nn) {
    size_t n4 = (size_t)Nn * 32;   // number of float4 in g_agg
    float4* a4 = reinterpret_cast<float4*>(g_agg);
    size_t i = (size_t)blockIdx.x * blockDim.x + threadIdx.x;
    size_t stride = (size_t)gridDim.x * blockDim.x;
    float4 z = make_float4(0.f, 0.f, 0.f, 0.f);
    for (; i < n4; i += stride) a4[i] = z;
    if (blockIdx.x == 0 && threadIdx.x < 128) {
        g_s1[threadIdx.x] = 0.0; g_q1[threadIdx.x] = 0.0;
        g_s2[threadIdx.x] = 0.0; g_q2[threadIdx.x] = 0.0;
    }
}

__global__ void finalize_bn(int which, const float* __restrict__ g,
                            const float* __restrict__ be, int M) {
    int c = threadIdx.x;
    double s = which ? g_s2[c] : g_s1[c];
    double q = which ? g_q2[c] : g_q1[c];
    double mean = s / (double)M;
    double var  = q / (double)M - mean * mean;
    float sc = g[c] * rsqrtf((float)var + 1e-5f);
    float sh = be[c] - (float)mean * sc;
    if (which) { g_scale2[c] = sc; g_shift2[c] = sh; }
    else       { g_scale1[c] = sc; g_shift1[c] = sh; }
}

// ---------------------------------------------------------------------------
// Tiled GEMM, block tile 128x128, BK=32, thread tile 8x8, 256 threads.
// MODE 0: A = gather(h[src]||h[dst]||ea), epi: store X1 + col stats (s1/q1)
// MODE 1: A = relu(X1*scale1+shift1),     epi: atomicAdd into g_agg[dst]
// MODE 2: A = (h || g_agg),               epi: store Y + col stats (s2/q2)
// MODE 3: A = relu(Y*scale2+shift2),      epi: +b4 +h, row LayerNorm -> out
// ---------------------------------------------------------------------------
template <int MODE, int KDIM>
__global__ void __launch_bounds__(256) gemm_k(GP p) {
    __shared__ float As[128][33];
    __shared__ float Bs[32][128];

    const int tid = threadIdx.x;
    const int bm  = blockIdx.x * 128;
    const int rg  = tid >> 4;        // 0..15 row group (8 rows each)
    const int cg  = tid & 15;        // 0..15 col group
    const int m0  = rg * 8;
    const int n0a = cg * 4;          // cols n0a..n0a+3
    const int n0b = cg * 4 + 64;     // cols n0b..n0b+3

    float acc[8][8];
#pragma unroll
    for (int i = 0; i < 8; i++)
#pragma unroll
        for (int j = 0; j < 8; j++) acc[i][j] = 0.f;

    for (int k0 = 0; k0 < KDIM; k0 += 32) {
        // ---- load A tile (128 x 32), 4 float4 per thread ----
#pragma unroll
        for (int pp = 0; pp < 4; pp++) {
            int idx = tid + pp * 256;
            int r   = idx >> 3;
            int c4  = (idx & 7) << 2;
            int gm  = bm + r;
            int k   = k0 + c4;
            float4 v = make_float4(0.f, 0.f, 0.f, 0.f);
            if (gm < p.M) {
                if (MODE == 0) {
                    const float* ptr;
                    if (k < 128)      ptr = p.h  + (size_t)__ldg(&p.src[gm]) * 128 + k;
                    else if (k < 256) ptr = p.h  + (size_t)__ldg(&p.dst[gm]) * 128 + (k - 128);
                    else              ptr = p.ea + (size_t)gm * 64 + (k - 256);
                    v = *reinterpret_cast<const float4*>(ptr);
                } else if (MODE == 1) {
                    v = *reinterpret_cast<const float4*>(g_X1 + (size_t)gm * 128 + k);
                    v.x = fmaxf(0.f, fmaf(v.x, g_scale1[k + 0], g_shift1[k + 0]));
                    v.y = fmaxf(0.f, fmaf(v.y, g_scale1[k + 1], g_shift1[k + 1]));
                    v.z = fmaxf(0.f, fmaf(v.z, g_scale1[k + 2], g_shift1[k + 2]));
                    v.w = fmaxf(0.f, fmaf(v.w, g_scale1[k + 3], g_shift1[k + 3]));
                } else if (MODE == 2) {
                    if (k < 128) v = *reinterpret_cast<const float4*>(p.h + (size_t)gm * 128 + k);
                    else         v = *reinterpret_cast<const float4*>(g_agg + (size_t)gm * 128 + (k - 128));
                } else {
                    v = *reinterpret_cast<const float4*>(g_Y + (size_t)gm * 128 + k);
                    v.x = fmaxf(0.f, fmaf(v.x, g_scale2[k + 0], g_shift2[k + 0]));
                    v.y = fmaxf(0.f, fmaf(v.y, g_scale2[k + 1], g_shift2[k + 1]));
                    v.z = fmaxf(0.f, fmaf(v.z, g_scale2[k + 2], g_shift2[k + 2]));
                    v.w = fmaxf(0.f, fmaf(v.w, g_scale2[k + 3], g_shift2[k + 3]));
                }
            }
            As[r][c4 + 0] = v.x; As[r][c4 + 1] = v.y;
            As[r][c4 + 2] = v.z; As[r][c4 + 3] = v.w;
        }
        // ---- load B tile (32 x 128) from W ----
#pragma unroll
        for (int pp = 0; pp < 4; pp++) {
            int idx = tid + pp * 256;
            int r   = idx >> 5;
            int c4  = (idx & 31) << 2;
            float4 w = *reinterpret_cast<const float4*>(p.W + (size_t)(k0 + r) * 128 + c4);
            *reinterpret_cast<float4*>(&Bs[r][c4]) = w;
        }
        __syncthreads();

#pragma unroll 8
        for (int k = 0; k < 32; k++) {
            float a[8];
#pragma unroll
            for (int i = 0; i < 8; i++) a[i] = As[m0 + i][k];
            float4 b0 = *reinterpret_cast<const float4*>(&Bs[k][n0a]);
            float4 b1 = *reinterpret_cast<const float4*>(&Bs[k][n0b]);
#pragma unroll
            for (int i = 0; i < 8; i++) {
                acc[i][0] = fmaf(a[i], b0.x, acc[i][0]);
                acc[i][1] = fmaf(a[i], b0.y, acc[i][1]);
                acc[i][2] = fmaf(a[i], b0.z, acc[i][2]);
                acc[i][3] = fmaf(a[i], b0.w, acc[i][3]);
                acc[i][4] = fmaf(a[i], b1.x, acc[i][4]);
                acc[i][5] = fmaf(a[i], b1.y, acc[i][5]);
                acc[i][6] = fmaf(a[i], b1.z, acc[i][6]);
                acc[i][7] = fmaf(a[i], b1.w, acc[i][7]);
            }
        }
        __syncthreads();
    }

    // per-thread output column indices
    int ncol[8];
#pragma unroll
    for (int j = 0; j < 8; j++) ncol[j] = (j < 4) ? (n0a + j) : (n0b + j - 4);
    float bia[8];
#pragma unroll
    for (int j = 0; j < 8; j++) bia[j] = p.bias[ncol[j]];

    if (MODE == 0 || MODE == 2) {
        float* dstbuf = (MODE == 0) ? g_X1 : g_Y;
        float cs[8], cq[8];
#pragma unroll
        for (int j = 0; j < 8; j++) { cs[j] = 0.f; cq[j] = 0.f; }
#pragma unroll
        for (int i = 0; i < 8; i++) {
            int gm = bm + m0 + i;
            if (gm < p.M) {
                float v[8];
#pragma unroll
                for (int j = 0; j < 8; j++) v[j] = acc[i][j] + bia[j];
                float* row = dstbuf + (size_t)gm * 128;
                *reinterpret_cast<float4*>(row + n0a) = make_float4(v[0], v[1], v[2], v[3]);
                *reinterpret_cast<float4*>(row + n0b) = make_float4(v[4], v[5], v[6], v[7]);
#pragma unroll
                for (int j = 0; j < 8; j++) { cs[j] += v[j]; cq[j] += v[j] * v[j]; }
            }
        }
        // block-level column reduction through smem (reuse Bs)
        float* red = &Bs[0][0];
#pragma unroll
        for (int j = 0; j < 8; j++) red[rg * 128 + ncol[j]] = cs[j];
        __syncthreads();
        if (tid < 128) {
            double s = 0.0;
            for (int r2 = 0; r2 < 16; r2++) s += (double)red[r2 * 128 + tid];
            atomicAdd((MODE == 0) ? &g_s1[tid] : &g_s2[tid], s);
        }
        __syncthreads();
#pragma unroll
        for (int j = 0; j < 8; j++) red[rg * 128 + ncol[j]] = cq[j];
        __syncthreads();
        if (tid < 128) {
            double s = 0.0;
            for (int r2 = 0; r2 < 16; r2++) s += (double)red[r2 * 128 + tid];
            atomicAdd((MODE == 0) ? &g_q1[tid] : &g_q2[tid], s);
        }
    } else if (MODE == 1) {
#pragma unroll
        for (int i = 0; i < 8; i++) {
            int gm = bm + m0 + i;
            if (gm < p.M) {
                int d = __ldg(&p.dst[gm]);
                float* arow = g_agg + (size_t)d * 128;
#pragma unroll
                for (int j = 0; j < 8; j++) atomicAdd(arow + ncol[j], acc[i][j] + bia[j]);
            }
        }
    } else {  // MODE 3: +b4, residual, row LayerNorm
#pragma unroll
        for (int i = 0; i < 8; i++) {
            int gm = bm + m0 + i;
            bool ok = gm < p.M;
            float v[8];
            if (ok) {
                const float* hrow = p.h + (size_t)gm * 128;
                float4 h0 = *reinterpret_cast<const float4*>(hrow + n0a);
                float4 h1 = *reinterpret_cast<const float4*>(hrow + n0b);
                v[0] = acc[i][0] + bia[0] + h0.x;
                v[1] = acc[i][1] + bia[1] + h0.y;
                v[2] = acc[i][2] + bia[2] + h0.z;
                v[3] = acc[i][3] + bia[3] + h0.w;
                v[4] = acc[i][4] + bia[4] + h1.x;
                v[5] = acc[i][5] + bia[5] + h1.y;
                v[6] = acc[i][6] + bia[6] + h1.z;
                v[7] = acc[i][7] + bia[7] + h1.w;
            } else {
#pragma unroll
                for (int j = 0; j < 8; j++) v[j] = 0.f;
            }
            float rs = 0.f, rq = 0.f;
#pragma unroll
            for (int j = 0; j < 8; j++) { rs += v[j]; rq += v[j] * v[j]; }
            // row of 128 cols lives in one half-warp (16 lanes x 8 cols)
#pragma unroll
            for (int off = 8; off > 0; off >>= 1) {
                rs += __shfl_xor_sync(0xffffffffu, rs, off, 16);
                rq += __shfl_xor_sync(0xffffffffu, rq, off, 16);
            }
            float mean = rs * (1.f / 128.f);
            float var  = rq * (1.f / 128.f) - mean * mean;
            float rstd = rsqrtf(var + 1e-5f);
            if (ok) {
                float o[8];
#pragma unroll
                for (int j = 0; j < 8; j++)
                    o[j] = (v[j] - mean) * rstd * p.lng[ncol[j]] + p.lnb[ncol[j]];
                float* orow = p.out + (size_t)gm * 128;
                *reinterpret_cast<float4*>(orow + n0a) = make_float4(o[0], o[1], o[2], o[3]);
                *reinterpret_cast<float4*>(orow + n0b) = make_float4(o[4], o[5], o[6], o[7]);
            }
        }
    }
}

extern "C" void kernel_launch(void* const* d_in, const int* in_sizes, int n_in,
                              void* d_out, int out_size) {
    const float* h   = (const float*)d_in[0];
    const float* ea  = (const float*)d_in[1];
    const float* W1  = (const float*)d_in[2];
    const float* b1  = (const float*)d_in[3];
    const float* g1  = (const float*)d_in[4];
    const float* be1 = (const float*)d_in[5];
    const float* W2  = (const float*)d_in[6];
    const float* b2  = (const float*)d_in[7];
    const float* W3  = (const float*)d_in[8];
    const float* b3  = (const float*)d_in[9];
    const float* g2  = (const float*)d_in[10];
    const float* be2 = (const float*)d_in[11];
    const float* W4  = (const float*)d_in[12];
    const float* b4  = (const float*)d_in[13];
    const float* lng = (const float*)d_in[14];
    const float* lnb = (const float*)d_in[15];
    const int*   ei  = (const int*)d_in[16];

    const int E  = in_sizes[1] / 64;     // edge_attr [E, 64]
    const int Nn = in_sizes[0] / 128;    // h [N, 128]
    const int* src = ei;
    const int* dst = ei + E;
    float* out = (float*)d_out;

    const int nblkE = (E + 127) / 128;
    const int nblkN = (Nn + 127) / 128;

    zero_kernel<<<1024, 256>>>(Nn);

    GP p0; p0.h = h; p0.ea = ea; p0.W = W1; p0.bias = b1; p0.src = src; p0.dst = dst;
    p0.lng = nullptr; p0.lnb = nullptr; p0.out = nullptr; p0.M = E;
    gemm_k<0, 320><<<nblkE, 256>>>(p0);

    finalize_bn<<<1, 128>>>(0, g1, be1, E);

    GP p1; p1.h = nullptr; p1.ea = nullptr; p1.W = W2; p1.bias = b2; p1.src = src; p1.dst = dst;
    p1.lng = nullptr; p1.lnb = nullptr; p1.out = nullptr; p1.M = E;
    gemm_k<1, 128><<<nblkE, 256>>>(p1);

    GP p2; p2.h = h; p2.ea = nullptr; p2.W = W3; p2.bias = b3; p2.src = nullptr; p2.dst = nullptr;
    p2.lng = nullptr; p2.lnb = nullptr; p2.out = nullptr; p2.M = Nn;
    gemm_k<2, 256><<<nblkN, 256>>>(p2);

    finalize_bn<<<1, 128>>>(1, g2, be2, Nn);

    GP p3; p3.h = h; p3.ea = nullptr; p3.W = W4; p3.bias = b4; p3.src = nullptr; p3.dst = nullptr;
    p3.lng = lng; p3.lnb = lnb; p3.out = out; p3.M = Nn;
    gemm_k<3, 128><<<nblkN, 256>>>(p3);

    (void)n_in; (void)out_size;
}

// round 12
// speedup vs baseline: 1.4396x; 1.4396x over previous
#include <cuda_runtime.h>
#include <cstdint>

// ---------------------------------------------------------------------------
// PENN layer: message-passing GNN block.
//   X1 = [h[src] || h[dst] || e] @ W1 + b1            [E,128]  (+ col stats)
//   msg = relu(BN(X1)) @ W2 + b2 ; agg = scatter_sum(msg, dst)  [N,128]
//   Y  = [h || agg] @ W3 + b3                          [N,128]  (+ col stats)
//   hn = relu(BN(Y)) @ W4 + b4 ; out = LayerNorm(h + hn)        [N,128]
//
// R1: packed f32x2 FFMA inner loop (2x fp32 pipe), red.global.add.v4 scatter.
// R5: cp.async 2-stage pipeline for MODE0/2 (gather-latency hiding),
//     XOR-swizzled A smem layout (conflict-free + 16B-aligned for cp.async).
// R6-R11: resubmission (benches were infra GPU-acquisition timeouts).
// ---------------------------------------------------------------------------

static constexpr int MAXE = 640000;
static constexpr int MAXN = 50000;

__device__ __align__(16) float g_X1[(size_t)MAXE * 128];   // 327.68 MB
__device__ __align__(16) float g_Y [(size_t)MAXN * 128];   // 25.6 MB
__device__ __align__(16) float g_agg[(size_t)MAXN * 128];  // 25.6 MB
__device__ double g_s1[128], g_q1[128], g_s2[128], g_q2[128];
__device__ float  g_scale1[128], g_shift1[128], g_scale2[128], g_shift2[128];

struct GP {
    const float* h;
    const float* ea;
    const float* W;
    const float* bias;
    const int*   src;
    const int*   dst;
    const float* lng;
    const float* lnb;
    float*       out;
    int          M;
};

__device__ __forceinline__ unsigned long long pack2(float x, float y) {
    unsigned long long r;
    asm("mov.b64 %0, {%1, %2};" : "=l"(r) : "f"(x), "f"(y));
    return r;
}
__device__ __forceinline__ void unpack2(unsigned long long v, float& x, float& y) {
    asm("mov.b64 {%0, %1}, %2;" : "=f"(x), "=f"(y) : "l"(v));
}
// d = a * b + d  on packed f32x2 (identical rounding to scalar fmaf)
#define FFMA2(d, a, b) \
    asm("fma.rn.f32x2 %0, %1, %2, %0;" : "+l"(d) : "l"(a), "l"(b))

__device__ __forceinline__ void cp16(uint32_t dst, const void* src) {
    asm volatile("cp.async.cg.shared.global [%0], [%1], 16;" :: "r"(dst), "l"(src));
}
#define CP_COMMIT() asm volatile("cp.async.commit_group;")
#define CP_WAIT_1() asm volatile("cp.async.wait_group 1;")
#define CP_WAIT_0() asm volatile("cp.async.wait_group 0;")

__global__ void zero_kernel(int Nn) {
    size_t n4 = (size_t)Nn * 32;
    float4* a4 = reinterpret_cast<float4*>(g_agg);
    size_t i = (size_t)blockIdx.x * blockDim.x + threadIdx.x;
    size_t stride = (size_t)gridDim.x * blockDim.x;
    float4 z = make_float4(0.f, 0.f, 0.f, 0.f);
    for (; i < n4; i += stride) a4[i] = z;
    if (blockIdx.x == 0 && threadIdx.x < 128) {
        g_s1[threadIdx.x] = 0.0; g_q1[threadIdx.x] = 0.0;
        g_s2[threadIdx.x] = 0.0; g_q2[threadIdx.x] = 0.0;
    }
}

__global__ void finalize_bn(int which, const float* __restrict__ g,
                            const float* __restrict__ be, int M) {
    int c = threadIdx.x;
    double s = which ? g_s2[c] : g_s1[c];
    double q = which ? g_q2[c] : g_q1[c];
    double mean = s / (double)M;
    double var  = q / (double)M - mean * mean;
    float sc = g[c] * rsqrtf((float)var + 1e-5f);
    float sh = be[c] - (float)mean * sc;
    if (which) { g_scale2[c] = sc; g_shift2[c] = sh; }
    else       { g_scale1[c] = sc; g_shift1[c] = sh; }
}

// smem per stage: A tile 128x32 (swizzled, 16KB) + B tile 32x128 (16KB)
static constexpr int ASZ = 128 * 32;      // floats
static constexpr int BSZ = 32 * 128;      // floats
static constexpr int STG = ASZ + BSZ;     // 8192 floats = 32KB

// issue cp.asyncs for one (A,B) tile pair; no data in registers
template <int MODE>
__device__ __forceinline__ void prefetch_tile(const GP& p, uint32_t sA, uint32_t sB,
                                              int bm, int k0, int tid) {
#pragma unroll
    for (int pp = 0; pp < 4; pp++) {
        int idx = tid + pp * 256;
        int r   = idx >> 3;
        int c4  = (idx & 7) << 2;
        int gm  = bm + r;
        int k   = k0 + c4;
        // swizzled A offset: row r, chunk (c4/4) ^ (rg&7)
        uint32_t dst = sA + (uint32_t)(r * 32 + ((((c4 >> 2) ^ ((r >> 3) & 7)) << 2))) * 4u;
        if (gm < p.M) {
            const float* ptr;
            if (MODE == 0) {
                if (k < 128)      ptr = p.h  + (size_t)__ldg(&p.src[gm]) * 128 + k;
                else if (k < 256) ptr = p.h  + (size_t)__ldg(&p.dst[gm]) * 128 + (k - 128);
                else              ptr = p.ea + (size_t)gm * 64 + (k - 256);
            } else {  // MODE 2
                ptr = (k < 128) ? (p.h + (size_t)gm * 128 + k)
                                : (g_agg + (size_t)gm * 128 + (k - 128));
            }
            cp16(dst, ptr);
        }
        // OOB rows left stale: their accumulators are discarded in the epilogue.
    }
#pragma unroll
    for (int pp = 0; pp < 4; pp++) {
        int idx = tid + pp * 256;
        int r   = idx >> 5;
        int c4  = (idx & 31) << 2;
        cp16(sB + (uint32_t)(r * 128 + c4) * 4u, p.W + (size_t)(k0 + r) * 128 + c4);
    }
}

// ---------------------------------------------------------------------------
// Tiled GEMM, block tile 128x128, BK=32, thread tile 8x8, 256 threads.
// MODE 0: A = gather(h[src]||h[dst]||ea)  [cp.async pipe], epi: X1 + stats
// MODE 1: A = relu(X1*scale1+shift1)      [classic],       epi: red.v4 scatter
// MODE 2: A = (h || g_agg)                [cp.async pipe], epi: Y + stats
// MODE 3: A = relu(Y*scale2+shift2)       [classic],       epi: LN -> out
// ---------------------------------------------------------------------------
template <int MODE, int KDIM>
__global__ void __launch_bounds__(256) gemm_k(GP p) {
    extern __shared__ float sm[];
    constexpr int  T    = KDIM / 32;
    constexpr bool PIPE = (MODE == 0 || MODE == 2);

    const int tid = threadIdx.x;
    const int bm  = blockIdx.x * 128;
    const int rg  = tid >> 4;        // 0..15 row group (8 rows each)
    const int cg  = tid & 15;        // 0..15 col group
    const int m0  = rg * 8;
    const int n0a = cg * 4;
    const int n0b = cg * 4 + 64;
    const int swz = rg & 7;          // A-read swizzle factor

    uint32_t smem_u32 = (uint32_t)__cvta_generic_to_shared(sm);

    unsigned long long acc2[8][4];
#pragma unroll
    for (int i = 0; i < 8; i++)
#pragma unroll
        for (int j = 0; j < 4; j++) acc2[i][j] = 0ull;

    if (PIPE) {
        prefetch_tile<MODE>(p, smem_u32, smem_u32 + ASZ * 4u, bm, 0, tid);
        CP_COMMIT();
    }

    for (int t = 0; t < T; t++) {
        float* As = sm + (PIPE ? (t & 1) * STG : 0);
        float* Bs = As + ASZ;

        if (PIPE) {
            if (t + 1 < T) {
                uint32_t sb = smem_u32 + (uint32_t)(((t + 1) & 1) * STG) * 4u;
                prefetch_tile<MODE>(p, sb, sb + ASZ * 4u, bm, (t + 1) * 32, tid);
                CP_COMMIT();
                CP_WAIT_1();
            } else {
                CP_WAIT_0();
            }
            __syncthreads();
        } else {
            const int k0 = t * 32;
            // ---- classic load A tile with BN+ReLU transform ----
#pragma unroll
            for (int pp = 0; pp < 4; pp++) {
                int idx = tid + pp * 256;
                int r   = idx >> 3;
                int c4  = (idx & 7) << 2;
                int gm  = bm + r;
                int k   = k0 + c4;
                float4 v = make_float4(0.f, 0.f, 0.f, 0.f);
                if (gm < p.M) {
                    if (MODE == 1) {
                        v = *reinterpret_cast<const float4*>(g_X1 + (size_t)gm * 128 + k);
                        v.x = fmaxf(0.f, fmaf(v.x, g_scale1[k + 0], g_shift1[k + 0]));
                        v.y = fmaxf(0.f, fmaf(v.y, g_scale1[k + 1], g_shift1[k + 1]));
                        v.z = fmaxf(0.f, fmaf(v.z, g_scale1[k + 2], g_shift1[k + 2]));
                        v.w = fmaxf(0.f, fmaf(v.w, g_scale1[k + 3], g_shift1[k + 3]));
                    } else {  // MODE 3
                        v = *reinterpret_cast<const float4*>(g_Y + (size_t)gm * 128 + k);
                        v.x = fmaxf(0.f, fmaf(v.x, g_scale2[k + 0], g_shift2[k + 0]));
                        v.y = fmaxf(0.f, fmaf(v.y, g_scale2[k + 1], g_shift2[k + 1]));
                        v.z = fmaxf(0.f, fmaf(v.z, g_scale2[k + 2], g_shift2[k + 2]));
                        v.w = fmaxf(0.f, fmaf(v.w, g_scale2[k + 3], g_shift2[k + 3]));
                    }
                }
                int base = r * 32 + (((c4 >> 2) ^ ((r >> 3) & 7)) << 2);
                *reinterpret_cast<float4*>(&As[base]) = v;
            }
            // ---- load B tile ----
#pragma unroll
            for (int pp = 0; pp < 4; pp++) {
                int idx = tid + pp * 256;
                int r   = idx >> 5;
                int c4  = (idx & 31) << 2;
                float4 w = *reinterpret_cast<const float4*>(p.W + (size_t)(k0 + r) * 128 + c4);
                *reinterpret_cast<float4*>(&Bs[r * 128 + c4]) = w;
            }
            __syncthreads();
        }

#pragma unroll 8
        for (int k = 0; k < 32; k++) {
            const int koff = ((((k >> 2) ^ swz) << 2) | (k & 3));
            const ulonglong2 bb0 = *reinterpret_cast<const ulonglong2*>(&Bs[k * 128 + n0a]);
            const ulonglong2 bb1 = *reinterpret_cast<const ulonglong2*>(&Bs[k * 128 + n0b]);
#pragma unroll
            for (int i = 0; i < 8; i++) {
                float a = As[(m0 + i) * 32 + koff];
                unsigned long long aa = pack2(a, a);
                FFMA2(acc2[i][0], aa, bb0.x);
                FFMA2(acc2[i][1], aa, bb0.y);
                FFMA2(acc2[i][2], aa, bb1.x);
                FFMA2(acc2[i][3], aa, bb1.y);
            }
        }
        __syncthreads();
    }

    float acc[8][8];
#pragma unroll
    for (int i = 0; i < 8; i++) {
        unpack2(acc2[i][0], acc[i][0], acc[i][1]);
        unpack2(acc2[i][1], acc[i][2], acc[i][3]);
        unpack2(acc2[i][2], acc[i][4], acc[i][5]);
        unpack2(acc2[i][3], acc[i][6], acc[i][7]);
    }

    int ncol[8];
#pragma unroll
    for (int j = 0; j < 8; j++) ncol[j] = (j < 4) ? (n0a + j) : (n0b + j - 4);
    float bia[8];
#pragma unroll
    for (int j = 0; j < 8; j++) bia[j] = p.bias[ncol[j]];

    if (MODE == 0 || MODE == 2) {
        float* dstbuf = (MODE == 0) ? g_X1 : g_Y;
        float cs[8], cq[8];
#pragma unroll
        for (int j = 0; j < 8; j++) { cs[j] = 0.f; cq[j] = 0.f; }
#pragma unroll
        for (int i = 0; i < 8; i++) {
            int gm = bm + m0 + i;
            if (gm < p.M) {
                float v[8];
#pragma unroll
                for (int j = 0; j < 8; j++) v[j] = acc[i][j] + bia[j];
                float* row = dstbuf + (size_t)gm * 128;
                *reinterpret_cast<float4*>(row + n0a) = make_float4(v[0], v[1], v[2], v[3]);
                *reinterpret_cast<float4*>(row + n0b) = make_float4(v[4], v[5], v[6], v[7]);
#pragma unroll
                for (int j = 0; j < 8; j++) { cs[j] += v[j]; cq[j] += v[j] * v[j]; }
            }
        }
        // block-level column reduction through smem (stage-0 B area, free now)
        float* red = sm + ASZ;
#pragma unroll
        for (int j = 0; j < 8; j++) red[rg * 128 + ncol[j]] = cs[j];
        __syncthreads();
        if (tid < 128) {
            double s = 0.0;
            for (int r2 = 0; r2 < 16; r2++) s += (double)red[r2 * 128 + tid];
            atomicAdd((MODE == 0) ? &g_s1[tid] : &g_s2[tid], s);
        }
        __syncthreads();
#pragma unroll
        for (int j = 0; j < 8; j++) red[rg * 128 + ncol[j]] = cq[j];
        __syncthreads();
        if (tid < 128) {
            double s = 0.0;
            for (int r2 = 0; r2 < 16; r2++) s += (double)red[r2 * 128 + tid];
            atomicAdd((MODE == 0) ? &g_q1[tid] : &g_q2[tid], s);
        }
    } else if (MODE == 1) {
#pragma unroll
        for (int i = 0; i < 8; i++) {
            int gm = bm + m0 + i;
            if (gm < p.M) {
                int d = __ldg(&p.dst[gm]);
                float* arow = g_agg + (size_t)d * 128;
                float v0 = acc[i][0] + bia[0], v1 = acc[i][1] + bia[1];
                float v2 = acc[i][2] + bia[2], v3 = acc[i][3] + bia[3];
                float v4 = acc[i][4] + bia[4], v5 = acc[i][5] + bia[5];
                float v6 = acc[i][6] + bia[6], v7 = acc[i][7] + bia[7];
                asm volatile("red.global.add.v4.f32 [%0], {%1, %2, %3, %4};"
                             :: "l"(arow + n0a), "f"(v0), "f"(v1), "f"(v2), "f"(v3)
                             : "memory");
                asm volatile("red.global.add.v4.f32 [%0], {%1, %2, %3, %4};"
                             :: "l"(arow + n0b), "f"(v4), "f"(v5), "f"(v6), "f"(v7)
                             : "memory");
            }
        }
    } else {  // MODE 3: +b4, residual, row LayerNorm
#pragma unroll
        for (int i = 0; i < 8; i++) {
            int gm = bm + m0 + i;
            bool ok = gm < p.M;
            float v[8];
            if (ok) {
                const float* hrow = p.h + (size_t)gm * 128;
                float4 h0 = *reinterpret_cast<const float4*>(hrow + n0a);
                float4 h1 = *reinterpret_cast<const float4*>(hrow + n0b);
                v[0] = acc[i][0] + bia[0] + h0.x;
                v[1] = acc[i][1] + bia[1] + h0.y;
                v[2] = acc[i][2] + bia[2] + h0.z;
                v[3] = acc[i][3] + bia[3] + h0.w;
                v[4] = acc[i][4] + bia[4] + h1.x;
                v[5] = acc[i][5] + bia[5] + h1.y;
                v[6] = acc[i][6] + bia[6] + h1.z;
                v[7] = acc[i][7] + bia[7] + h1.w;
            } else {
#pragma unroll
                for (int j = 0; j < 8; j++) v[j] = 0.f;
            }
            float rs = 0.f, rq = 0.f;
#pragma unroll
            for (int j = 0; j < 8; j++) { rs += v[j]; rq += v[j] * v[j]; }
#pragma unroll
            for (int off = 8; off > 0; off >>= 1) {
                rs += __shfl_xor_sync(0xffffffffu, rs, off, 16);
                rq += __shfl_xor_sync(0xffffffffu, rq, off, 16);
            }
            float mean = rs * (1.f / 128.f);
            float var  = rq * (1.f / 128.f) - mean * mean;
            float rstd = rsqrtf(var + 1e-5f);
            if (ok) {
                float o[8];
#pragma unroll
                for (int j = 0; j < 8; j++)
                    o[j] = (v[j] - mean) * rstd * p.lng[ncol[j]] + p.lnb[ncol[j]];
                float* orow = p.out + (size_t)gm * 128;
                *reinterpret_cast<float4*>(orow + n0a) = make_float4(o[0], o[1], o[2], o[3]);
                *reinterpret_cast<float4*>(orow + n0b) = make_float4(o[4], o[5], o[6], o[7]);
            }
        }
    }
}

extern "C" void kernel_launch(void* const* d_in, const int* in_sizes, int n_in,
                              void* d_out, int out_size) {
    const float* h   = (const float*)d_in[0];
    const float* ea  = (const float*)d_in[1];
    const float* W1  = (const float*)d_in[2];
    const float* b1  = (const float*)d_in[3];
    const float* g1  = (const float*)d_in[4];
    const float* be1 = (const float*)d_in[5];
    const float* W2  = (const float*)d_in[6];
    const float* b2  = (const float*)d_in[7];
    const float* W3  = (const float*)d_in[8];
    const float* b3  = (const float*)d_in[9];
    const float* g2  = (const float*)d_in[10];
    const float* be2 = (const float*)d_in[11];
    const float* W4  = (const float*)d_in[12];
    const float* b4  = (const float*)d_in[13];
    const float* lng = (const float*)d_in[14];
    const float* lnb = (const float*)d_in[15];
    const int*   ei  = (const int*)d_in[16];

    const int E  = in_sizes[1] / 64;     // edge_attr [E, 64]
    const int Nn = in_sizes[0] / 128;    // h [N, 128]
    const int* src = ei;
    const int* dst = ei + E;
    float* out = (float*)d_out;

    const int nblkE = (E + 127) / 128;
    const int nblkN = (Nn + 127) / 128;

    const int SM_PIPE = 2 * STG * 4;   // 65536 B
    const int SM_ONE  = STG * 4;       // 32768 B
    cudaFuncSetAttribute(gemm_k<0, 320>, cudaFuncAttributeMaxDynamicSharedMemorySize, SM_PIPE);
    cudaFuncSetAttribute(gemm_k<2, 256>, cudaFuncAttributeMaxDynamicSharedMemorySize, SM_PIPE);

    zero_kernel<<<1024, 256>>>(Nn);

    GP p0; p0.h = h; p0.ea = ea; p0.W = W1; p0.bias = b1; p0.src = src; p0.dst = dst;
    p0.lng = nullptr; p0.lnb = nullptr; p0.out = nullptr; p0.M = E;
    gemm_k<0, 320><<<nblkE, 256, SM_PIPE>>>(p0);

    finalize_bn<<<1, 128>>>(0, g1, be1, E);

    GP p1; p1.h = nullptr; p1.ea = nullptr; p1.W = W2; p1.bias = b2; p1.src = src; p1.dst = dst;
    p1.lng = nullptr; p1.lnb = nullptr; p1.out = nullptr; p1.M = E;
    gemm_k<1, 128><<<nblkE, 256, SM_ONE>>>(p1);

    GP p2; p2.h = h; p2.ea = nullptr; p2.W = W3; p2.bias = b3; p2.src = nullptr; p2.dst = nullptr;
    p2.lng = nullptr; p2.lnb = nullptr; p2.out = nullptr; p2.M = Nn;
    gemm_k<2, 256><<<nblkN, 256, SM_PIPE>>>(p2);

    finalize_bn<<<1, 128>>>(1, g2, be2, Nn);

    GP p3; p3.h = h; p3.ea = nullptr; p3.W = W4; p3.bias = b4; p3.src = nullptr; p3.dst = nullptr;
    p3.lng = lng; p3.lnb = lnb; p3.out = out; p3.M = Nn;
    gemm_k<3, 128><<<nblkN, 256, SM_ONE>>>(p3);

    (void)n_in; (void)out_size;
}